// round 1
// baseline (speedup 1.0000x reference)
#include <cuda_runtime.h>
#include <math.h>
#include <stdint.h>
#include <stddef.h>

// ---------------------------------------------------------------------------
// GCViT block, fp32 baseline.
// Shapes: B=32, H=W=64, C=192, NH=6, hd=32, WS=8, N=64, Bw=2048, M=131072.
// ---------------------------------------------------------------------------

#define M_ROWS   131072      // Bw * N  == B*H*W tokens
#define C_DIM    192
#define KV_DIM   384
#define HID_DIM  768
#define NH_      6
#define HD_      32
#define N_WIN    64          // tokens per window

// Scratch (device globals: allocation-free per harness rules)
__device__ float g_h  [(size_t)M_ROWS * C_DIM];    // LN output (reused for LN2)
__device__ float g_kv [(size_t)M_ROWS * KV_DIM];   // K|V projection
__device__ float g_o  [(size_t)M_ROWS * C_DIM];    // attention output
__device__ float g_y  [(size_t)M_ROWS * C_DIM];    // first residual (window order)
__device__ float g_hid[(size_t)M_ROWS * HID_DIM];  // MLP hidden
__device__ float g_bias[NH_ * N_WIN * N_WIN];      // expanded rel-pos bias

// window-order row r -> pixel-order row p
__device__ __forceinline__ int remap_row(int r) {
    int w = r >> 6, n = r & 63;
    int b = w >> 6, wy = (w >> 3) & 7, wx = w & 7;
    int iy = n >> 3, ix = n & 7;
    return (b * 64 + wy * 8 + iy) * 64 + wx * 8 + ix;
}

// ---------------------------------------------------------------------------
// Kernel: expand relative-position bias table -> [NH, 64, 64]
// ---------------------------------------------------------------------------
__global__ void bias_kernel(const float* __restrict__ rpb, float* __restrict__ bias) {
    int h = blockIdx.x;
    for (int i = threadIdx.x; i < N_WIN * N_WIN; i += blockDim.x) {
        int n = i >> 6, m = i & 63;
        int ry = (n >> 3) - (m >> 3) + 7;
        int rx = (n & 7) - (m & 7) + 7;
        bias[h * 4096 + i] = rpb[(ry * 15 + rx) * NH_ + h];
    }
}

// ---------------------------------------------------------------------------
// Kernel: LayerNorm, one warp per token, 6 channels per lane.
// REMAP_IN: read input at pixel-order row (LN1 + window partition).
// ---------------------------------------------------------------------------
template <bool REMAP_IN>
__global__ void ln_kernel(const float* __restrict__ in,
                          const float* __restrict__ gamma,
                          const float* __restrict__ beta,
                          float* __restrict__ out) {
    int warp = threadIdx.x >> 5;
    int lane = threadIdx.x & 31;
    int r = blockIdx.x * 8 + warp;            // window-order row
    int in_row = REMAP_IN ? remap_row(r) : r;
    const float* px = in + (size_t)in_row * C_DIM;

    float v[6];
    float s = 0.f, s2 = 0.f;
#pragma unroll
    for (int t = 0; t < 6; t++) {
        v[t] = px[lane + t * 32];
        s  += v[t];
        s2 += v[t] * v[t];
    }
#pragma unroll
    for (int off = 16; off > 0; off >>= 1) {
        s  += __shfl_xor_sync(0xffffffffu, s,  off);
        s2 += __shfl_xor_sync(0xffffffffu, s2, off);
    }
    float mean = s * (1.f / C_DIM);
    float var  = s2 * (1.f / C_DIM) - mean * mean;
    float rstd = rsqrtf(var + 1e-5f);

    float* po = out + (size_t)r * C_DIM;
#pragma unroll
    for (int t = 0; t < 6; t++) {
        int c = lane + t * 32;
        po[c] = (v[t] - mean) * rstd * gamma[c] + beta[c];
    }
}

// ---------------------------------------------------------------------------
// Kernel: tiled fp32 GEMM  C[M,N] = A[M,K] @ B[K,N]  (+ epilogue)
//   BM=128 BN=64 BK=16, 256 threads, 8x4 register tile.
// EPI: 0 = +bias (KV)
//      1 = +bias + x[remap(r)] residual -> y (window order)   (proj)
//      2 = gelu(+bias)                                        (fc1)
//      3 = +bias + y[r], scatter to out[remap(r)]             (fc2)
// ---------------------------------------------------------------------------
template <int EPI>
__global__ __launch_bounds__(256)
void gemm_kernel(const float* __restrict__ A, const float* __restrict__ B,
                 const float* __restrict__ bias, float* __restrict__ C,
                 const float* __restrict__ res, int N, int K) {
    constexpr int BM = 128, BN = 64, BK = 16;
    __shared__ float As[BK][BM + 4];
    __shared__ float Bs[BK][BN];

    const int bm = blockIdx.y * BM;
    const int bn = blockIdx.x * BN;
    const int tid = threadIdx.x;
    const int tr = (tid >> 4) << 3;   // 0..120 step 8
    const int tc = (tid & 15) << 2;   // 0..60  step 4

    float acc[8][4];
#pragma unroll
    for (int i = 0; i < 8; i++)
#pragma unroll
        for (int j = 0; j < 4; j++) acc[i][j] = 0.f;

    for (int k0 = 0; k0 < K; k0 += BK) {
        // load A tile: 128 rows x 16 cols = 512 float4
#pragma unroll
        for (int it = 0; it < 2; it++) {
            int idx = tid + it * 256;
            int row = idx >> 2;
            int c4  = idx & 3;
            float4 v = *(const float4*)(A + (size_t)(bm + row) * K + k0 + c4 * 4);
            As[c4 * 4 + 0][row] = v.x;
            As[c4 * 4 + 1][row] = v.y;
            As[c4 * 4 + 2][row] = v.z;
            As[c4 * 4 + 3][row] = v.w;
        }
        // load B tile: 16 rows x 64 cols = 256 float4
        {
            int row = tid >> 4;
            int c4  = tid & 15;
            float4 v = *(const float4*)(B + (size_t)(k0 + row) * N + bn + c4 * 4);
            *(float4*)&Bs[row][c4 * 4] = v;
        }
        __syncthreads();

#pragma unroll
        for (int kk = 0; kk < BK; kk++) {
            float a[8], b[4];
#pragma unroll
            for (int i = 0; i < 8; i++) a[i] = As[kk][tr + i];
#pragma unroll
            for (int j = 0; j < 4; j++) b[j] = Bs[kk][tc + j];
#pragma unroll
            for (int i = 0; i < 8; i++)
#pragma unroll
                for (int j = 0; j < 4; j++) acc[i][j] += a[i] * b[j];
        }
        __syncthreads();
    }

#pragma unroll
    for (int i = 0; i < 8; i++) {
        int r = bm + tr + i;
        int p = (EPI == 1 || EPI == 3) ? remap_row(r) : r;
#pragma unroll
        for (int j = 0; j < 4; j++) {
            int c = bn + tc + j;
            float v = acc[i][j] + bias[c];
            if (EPI == 0) {
                C[(size_t)r * N + c] = v;
            } else if (EPI == 1) {
                C[(size_t)r * N + c] = v + res[(size_t)p * N + c];
            } else if (EPI == 2) {
                C[(size_t)r * N + c] = 0.5f * v * (1.f + erff(v * 0.70710678118654752f));
            } else { // EPI == 3
                C[(size_t)p * N + c] = v + res[(size_t)r * N + c];
            }
        }
    }
}

// ---------------------------------------------------------------------------
// Kernel: windowed attention with global query.
// grid = (Bw=2048, NH=6), block = 64 threads (thread n = query row n).
// ---------------------------------------------------------------------------
__global__ __launch_bounds__(64)
void attn_kernel(const float* __restrict__ kv, const float* __restrict__ qg,
                 const float* __restrict__ bias, float* __restrict__ obuf) {
    const int w = blockIdx.x;
    const int h = blockIdx.y;
    const int n = threadIdx.x;
    const int b = w >> 6;

    __shared__ float sk[64][32];
    __shared__ float sv[64][32];

    const float* krow = kv + ((size_t)(w * 64 + n)) * KV_DIM + h * HD_;
#pragma unroll
    for (int d4 = 0; d4 < 8; d4++) {
        ((float4*)sk[n])[d4] = ((const float4*)krow)[d4];
        ((float4*)sv[n])[d4] = ((const float4*)(krow + C_DIM))[d4];
    }

    float q[HD_];
    const float* qrow = qg + (((size_t)(b * 64 + n)) * NH_ + h) * HD_;
    const float scale = 0.17677669529663687f;   // 1/sqrt(32)
#pragma unroll
    for (int d = 0; d < HD_; d++) q[d] = qrow[d] * scale;
    __syncthreads();

    float sc[64];
    float mx = -3.0e38f;
    const float* brow = bias + (h * 64 + n) * 64;
#pragma unroll 4
    for (int m = 0; m < 64; m++) {
        float s = brow[m];
#pragma unroll
        for (int d = 0; d < HD_; d++) s += q[d] * sk[m][d];
        sc[m] = s;
        mx = fmaxf(mx, s);
    }
    float sum = 0.f;
#pragma unroll 8
    for (int m = 0; m < 64; m++) {
        sc[m] = __expf(sc[m] - mx);
        sum += sc[m];
    }
    float o[HD_];
#pragma unroll
    for (int d = 0; d < HD_; d++) o[d] = 0.f;
#pragma unroll 4
    for (int m = 0; m < 64; m++) {
        float p = sc[m];
#pragma unroll
        for (int d = 0; d < HD_; d++) o[d] += p * sv[m][d];
    }
    float inv = 1.f / sum;
    float* orow = obuf + ((size_t)(w * 64 + n)) * C_DIM + h * HD_;
#pragma unroll
    for (int d4 = 0; d4 < 8; d4++) {
        float4 v;
        v.x = o[d4 * 4 + 0] * inv;
        v.y = o[d4 * 4 + 1] * inv;
        v.z = o[d4 * 4 + 2] * inv;
        v.w = o[d4 * 4 + 3] * inv;
        ((float4*)orow)[d4] = v;
    }
}

// ---------------------------------------------------------------------------
// Launch
// ---------------------------------------------------------------------------
extern "C" void kernel_launch(void* const* d_in, const int* in_sizes, int n_in,
                              void* d_out, int out_size) {
    const float* x      = (const float*)d_in[0];
    const float* qg     = (const float*)d_in[1];
    const float* n1g    = (const float*)d_in[2];
    const float* n1b    = (const float*)d_in[3];
    const float* qkv_w  = (const float*)d_in[4];
    const float* qkv_b  = (const float*)d_in[5];
    const float* rpb    = (const float*)d_in[6];
    const float* proj_w = (const float*)d_in[7];
    const float* proj_b = (const float*)d_in[8];
    const float* n2g    = (const float*)d_in[9];
    const float* n2b    = (const float*)d_in[10];
    const float* fc1_w  = (const float*)d_in[11];
    const float* fc1_b  = (const float*)d_in[12];
    const float* fc2_w  = (const float*)d_in[13];
    const float* fc2_b  = (const float*)d_in[14];
    float* out = (float*)d_out;

    float *ph, *pkv, *po, *py, *phid, *pbias;
    cudaGetSymbolAddress((void**)&ph,    g_h);
    cudaGetSymbolAddress((void**)&pkv,   g_kv);
    cudaGetSymbolAddress((void**)&po,    g_o);
    cudaGetSymbolAddress((void**)&py,    g_y);
    cudaGetSymbolAddress((void**)&phid,  g_hid);
    cudaGetSymbolAddress((void**)&pbias, g_bias);

    // 1) expand relative-position bias
    bias_kernel<<<NH_, 256>>>(rpb, pbias);
    // 2) LN1 + window partition (pixel -> window order)
    ln_kernel<true><<<M_ROWS / 8, 256>>>(x, n1g, n1b, ph);
    // 3) KV projection
    gemm_kernel<0><<<dim3(KV_DIM / 64, M_ROWS / 128), 256>>>(ph, qkv_w, qkv_b, pkv, nullptr, KV_DIM, C_DIM);
    // 4) attention
    attn_kernel<<<dim3(2048, NH_), 64>>>(pkv, qg, pbias, po);
    // 5) proj + residual (x gathered via remap); y kept in window order
    gemm_kernel<1><<<dim3(C_DIM / 64, M_ROWS / 128), 256>>>(po, proj_w, proj_b, py, x, C_DIM, C_DIM);
    // 6) LN2 (window order in/out)
    ln_kernel<false><<<M_ROWS / 8, 256>>>(py, n2g, n2b, ph);
    // 7) fc1 + GELU
    gemm_kernel<2><<<dim3(HID_DIM / 64, M_ROWS / 128), 256>>>(ph, fc1_w, fc1_b, phid, nullptr, HID_DIM, C_DIM);
    // 8) fc2 + residual, scatter to pixel order
    gemm_kernel<3><<<dim3(C_DIM / 64, M_ROWS / 128), 256>>>(phid, fc2_w, fc2_b, out, py, C_DIM, HID_DIM);
}

// round 7
// speedup vs baseline: 2.1493x; 2.1493x over previous
#include <cuda_runtime.h>
#include <cuda_fp16.h>
#include <mma.h>
#include <math.h>
#include <stdint.h>
#include <stddef.h>

using namespace nvcuda;

// ---------------------------------------------------------------------------
// GCViT block. fp16 WMMA GEMMs (no inline PTX anywhere) + fp32 LN/attention.
// Shapes: B=32, H=W=64, C=192, NH=6, hd=32, WS=8, N=64, Bw=2048, M=131072.
// ---------------------------------------------------------------------------

#define M_ROWS   131072
#define C_DIM    192
#define KV_DIM   384
#define HID_DIM  768
#define NH_      6
#define HD_      32

// Scratch (device globals; allocation-free per harness rules)
__device__ __half g_h  [(size_t)M_ROWS * C_DIM];    // LN out (fp16)
__device__ __half g_kv [(size_t)M_ROWS * KV_DIM];   // K|V (fp16)
__device__ __half g_o  [(size_t)M_ROWS * C_DIM];    // attn out (fp16)
__device__ float  g_y  [(size_t)M_ROWS * C_DIM];    // residual-1 (fp32, window order)
__device__ __half g_hid[(size_t)M_ROWS * HID_DIM];  // MLP hidden (fp16)
__device__ float  g_bias[NH_ * 64 * 64];
// transposed fp16 weights [N,K]
__device__ __half g_wkv [KV_DIM  * C_DIM];
__device__ __half g_wpr [C_DIM   * C_DIM];
__device__ __half g_wf1 [HID_DIM * C_DIM];
__device__ __half g_wf2 [C_DIM   * HID_DIM];

__device__ __forceinline__ int remap_row(int r) {
    int w = r >> 6, n = r & 63;
    int b = w >> 6, wy = (w >> 3) & 7, wx = w & 7;
    int iy = n >> 3, ix = n & 7;
    return (b * 64 + wy * 8 + iy) * 64 + wx * 8 + ix;
}

// ---------------------------------------------------------------------------
// bias expand
// ---------------------------------------------------------------------------
__global__ void bias_kernel(const float* __restrict__ rpb, float* __restrict__ bias) {
    int h = blockIdx.x;
    for (int i = threadIdx.x; i < 64 * 64; i += blockDim.x) {
        int n = i >> 6, m = i & 63;
        int ry = (n >> 3) - (m >> 3) + 7;
        int rx = (n & 7) - (m & 7) + 7;
        bias[h * 4096 + i] = rpb[(ry * 15 + rx) * NH_ + h];
    }
}

// ---------------------------------------------------------------------------
// weight transpose + convert: W[K,N] f32 -> Wt[N,K] fp16
// ---------------------------------------------------------------------------
__global__ void wt_kernel(const float* __restrict__ W, __half* __restrict__ Wt,
                          int K, int N) {
    __shared__ float t[32][33];
    int n0 = blockIdx.x * 32, k0 = blockIdx.y * 32;
    int tx = threadIdx.x, ty = threadIdx.y;   // 32 x 8
#pragma unroll
    for (int i = 0; i < 4; i++)
        t[ty * 4 + i][tx] = W[(size_t)(k0 + ty * 4 + i) * N + n0 + tx];
    __syncthreads();
#pragma unroll
    for (int i = 0; i < 4; i++)
        Wt[(size_t)(n0 + ty * 4 + i) * K + k0 + tx] = __float2half(t[tx][ty * 4 + i]);
}

// ---------------------------------------------------------------------------
// LayerNorm -> fp16.  REMAP_IN: gather from pixel order (LN1 + window part.)
// ---------------------------------------------------------------------------
template <bool REMAP_IN>
__global__ void ln_kernel(const float* __restrict__ in,
                          const float* __restrict__ gamma,
                          const float* __restrict__ beta,
                          __half* __restrict__ out) {
    int warp = threadIdx.x >> 5;
    int lane = threadIdx.x & 31;
    int r = blockIdx.x * 8 + warp;
    int in_row = REMAP_IN ? remap_row(r) : r;
    const float* px = in + (size_t)in_row * C_DIM;

    float v[6];
    float s = 0.f, s2 = 0.f;
#pragma unroll
    for (int t = 0; t < 6; t++) {
        v[t] = px[lane + t * 32];
        s += v[t]; s2 += v[t] * v[t];
    }
#pragma unroll
    for (int off = 16; off > 0; off >>= 1) {
        s  += __shfl_xor_sync(0xffffffffu, s,  off);
        s2 += __shfl_xor_sync(0xffffffffu, s2, off);
    }
    float mean = s * (1.f / C_DIM);
    float var  = s2 * (1.f / C_DIM) - mean * mean;
    float rstd = rsqrtf(var + 1e-5f);

    __half* po = out + (size_t)r * C_DIM;
#pragma unroll
    for (int t = 0; t < 6; t++) {
        int c = lane + t * 32;
        po[c] = __float2half((v[t] - mean) * rstd * gamma[c] + beta[c]);
    }
}

// ---------------------------------------------------------------------------
// WMMA GEMM: C[M,N] = A[M,K] @ Bt[N,K]^T  (A row-major, Bt N-major = B col-major)
// BM=128 BN=64 BK=32, 256 threads (8 warps: 4(M) x 2(N)), warp tile 32x32.
// Register-prefetch double buffering (no cp.async).
// EPI: 0 kv (+bias -> fp16)         1 proj (+bias + x[remap] -> f32 y)
//      2 fc1 (+bias, gelu -> fp16)  3 fc2 (+bias + y -> f32 out[remap])
// ---------------------------------------------------------------------------
#define A_LD 40     // 32 + 8 halves; row stride 80B (multiple of 16B)
#define S_LD 68     // f32 staging stride (272B, multiple of 16B)

template <int EPI>
__global__ __launch_bounds__(256)
void mm_kernel(const __half* __restrict__ A, const __half* __restrict__ Bt,
               const float* __restrict__ bias, void* __restrict__ Cout,
               const float* __restrict__ res, int N, int K) {
    __shared__ __align__(16) char smraw[30720];
    __half* As = (__half*)smraw;               // [2][128*40] = 20480 B
    __half* Bs = (__half*)(smraw + 20480);     // [2][64*40]  = 10240 B
    float*  stg = (float*)smraw;               // epilogue: 64 x 68 f32 = 17408 B

    const int tid = threadIdx.x;
    const int wid = tid >> 5;
    const int bm = blockIdx.y * 128;
    const int bn = blockIdx.x * 64;
    const int wm = (wid & 3) * 32;
    const int wn = (wid >> 2) * 32;

    wmma::fragment<wmma::accumulator, 16, 16, 16, float> acc[2][2];
#pragma unroll
    for (int mt = 0; mt < 2; mt++)
#pragma unroll
        for (int nt = 0; nt < 2; nt++) wmma::fill_fragment(acc[mt][nt], 0.f);

    const int nc = K >> 5;   // K/32

    // per-thread copy slots
    const int arow0 = tid >> 2,          aseg0 = tid & 3;          // + i*64 rows
    const int brow  = tid >> 2,          bseg  = tid & 3;

    // ---- chunk 0 direct to buffer 0
    {
#pragma unroll
        for (int i = 0; i < 2; i++) {
            int row = arow0 + i * 64;
            *(float4*)(As + row * A_LD + aseg0 * 8) =
                *(const float4*)(A + (size_t)(bm + row) * K + aseg0 * 8);
        }
        *(float4*)(Bs + brow * A_LD + bseg * 8) =
            *(const float4*)(Bt + (size_t)(bn + brow) * K + bseg * 8);
    }
    __syncthreads();

    float4 pa[2], pb;
    for (int c = 0; c < nc; c++) {
        int cur = c & 1;
        if (c + 1 < nc) {
            int koff = (c + 1) * 32;
#pragma unroll
            for (int i = 0; i < 2; i++) {
                int row = arow0 + i * 64;
                pa[i] = *(const float4*)(A + (size_t)(bm + row) * K + koff + aseg0 * 8);
            }
            pb = *(const float4*)(Bt + (size_t)(bn + brow) * K + koff + bseg * 8);
        }

        const __half* Ac = As + cur * 128 * A_LD;
        const __half* Bc = Bs + cur * 64 * A_LD;
#pragma unroll
        for (int ks = 0; ks < 2; ks++) {
            wmma::fragment<wmma::matrix_a, 16, 16, 16, __half, wmma::row_major> af[2];
            wmma::fragment<wmma::matrix_b, 16, 16, 16, __half, wmma::col_major> bf[2];
#pragma unroll
            for (int mt = 0; mt < 2; mt++)
                wmma::load_matrix_sync(af[mt], Ac + (wm + mt * 16) * A_LD + ks * 16, A_LD);
#pragma unroll
            for (int nt = 0; nt < 2; nt++)
                wmma::load_matrix_sync(bf[nt], Bc + (wn + nt * 16) * A_LD + ks * 16, A_LD);
#pragma unroll
            for (int mt = 0; mt < 2; mt++)
#pragma unroll
                for (int nt = 0; nt < 2; nt++)
                    wmma::mma_sync(acc[mt][nt], af[mt], bf[nt], acc[mt][nt]);
        }

        if (c + 1 < nc) {
            int nxt = cur ^ 1;
            __half* An = As + nxt * 128 * A_LD;
            __half* Bn = Bs + nxt * 64 * A_LD;
#pragma unroll
            for (int i = 0; i < 2; i++) {
                int row = arow0 + i * 64;
                *(float4*)(An + row * A_LD + aseg0 * 8) = pa[i];
            }
            *(float4*)(Bn + brow * A_LD + bseg * 8) = pb;
        }
        __syncthreads();
    }

    // ---- epilogue: two M-passes through f32 smem staging (coalesced writes)
#pragma unroll
    for (int p = 0; p < 2; p++) {
        if (((wid & 3) >> 1) == p) {
            int wrow = wm & 63;   // 0 or 32 within the pass
#pragma unroll
            for (int mt = 0; mt < 2; mt++)
#pragma unroll
                for (int nt = 0; nt < 2; nt++)
                    wmma::store_matrix_sync(stg + (wrow + mt * 16) * S_LD + wn + nt * 16,
                                            acc[mt][nt], S_LD, wmma::mem_row_major);
        }
        __syncthreads();

        int col = tid & 63;
        int rb  = tid >> 6;       // 0..3
        int gc  = bn + col;
        float bv = bias[gc];
#pragma unroll
        for (int j = 0; j < 16; j++) {
            int row  = rb * 16 + j;
            int grow = bm + p * 64 + row;
            float v  = stg[row * S_LD + col] + bv;
            if (EPI == 0) {
                ((__half*)Cout)[(size_t)grow * N + gc] = __float2half(v);
            } else if (EPI == 1) {
                int prow = remap_row(grow);
                ((float*)Cout)[(size_t)grow * N + gc] = v + res[(size_t)prow * N + gc];
            } else if (EPI == 2) {
                float g = 0.5f * v * (1.f + erff(v * 0.70710678118654752f));
                ((__half*)Cout)[(size_t)grow * N + gc] = __float2half(g);
            } else {
                int prow = remap_row(grow);
                ((float*)Cout)[(size_t)prow * N + gc] = v + res[(size_t)grow * N + gc];
            }
        }
        __syncthreads();
    }
}

// ---------------------------------------------------------------------------
// attention: block = one (window, head), 64 threads, single fused pass,
// no max-subtraction (logits are O(1)), fp16 KV in/out, fp32 math.
// ---------------------------------------------------------------------------
__global__ __launch_bounds__(64)
void attn_kernel(const __half* __restrict__ kv, const float* __restrict__ qg,
                 const float* __restrict__ bias, __half* __restrict__ obuf) {
    const int w = blockIdx.x;
    const int h = blockIdx.y;
    const int n = threadIdx.x;
    const int b = w >> 6;

    __shared__ float sk[64][32];
    __shared__ float sv[64][32];

    const __half* krow = kv + (size_t)(w * 64 + n) * KV_DIM + h * HD_;
#pragma unroll
    for (int i = 0; i < 16; i++) {
        float2 fk = __half22float2(((const __half2*)krow)[i]);
        float2 fv = __half22float2(((const __half2*)(krow + C_DIM))[i]);
        sk[n][2 * i] = fk.x; sk[n][2 * i + 1] = fk.y;
        sv[n][2 * i] = fv.x; sv[n][2 * i + 1] = fv.y;
    }

    float q[HD_];
    const float* qrow = qg + ((size_t)(b * 64 + n) * NH_ + h) * HD_;
    const float scale = 0.17677669529663687f;   // 1/sqrt(32)
#pragma unroll
    for (int d = 0; d < HD_; d++) q[d] = qrow[d] * scale;
    __syncthreads();

    float o[HD_];
#pragma unroll
    for (int d = 0; d < HD_; d++) o[d] = 0.f;
    float sum = 0.f;
    const float* brow = bias + (h * 64 + n) * 64;

#pragma unroll 4
    for (int m = 0; m < 64; m++) {
        const float4* k4 = (const float4*)sk[m];
        float s = brow[m];
#pragma unroll
        for (int d4 = 0; d4 < 8; d4++) {
            float4 kk = k4[d4];
            s += q[d4 * 4 + 0] * kk.x + q[d4 * 4 + 1] * kk.y
               + q[d4 * 4 + 2] * kk.z + q[d4 * 4 + 3] * kk.w;
        }
        float e = __expf(s);
        sum += e;
        const float4* v4 = (const float4*)sv[m];
#pragma unroll
        for (int d4 = 0; d4 < 8; d4++) {
            float4 vv = v4[d4];
            o[d4 * 4 + 0] += e * vv.x;
            o[d4 * 4 + 1] += e * vv.y;
            o[d4 * 4 + 2] += e * vv.z;
            o[d4 * 4 + 3] += e * vv.w;
        }
    }
    float inv = 1.f / sum;
    __half* orow = obuf + (size_t)(w * 64 + n) * C_DIM + h * HD_;
#pragma unroll
    for (int i = 0; i < 16; i++) {
        ((__half2*)orow)[i] = __floats2half2_rn(o[2 * i] * inv, o[2 * i + 1] * inv);
    }
}

// ---------------------------------------------------------------------------
// launch
// ---------------------------------------------------------------------------
extern "C" void kernel_launch(void* const* d_in, const int* in_sizes, int n_in,
                              void* d_out, int out_size) {
    const float* x      = (const float*)d_in[0];
    const float* qg     = (const float*)d_in[1];
    const float* n1g    = (const float*)d_in[2];
    const float* n1b    = (const float*)d_in[3];
    const float* qkv_w  = (const float*)d_in[4];
    const float* qkv_b  = (const float*)d_in[5];
    const float* rpb    = (const float*)d_in[6];
    const float* proj_w = (const float*)d_in[7];
    const float* proj_b = (const float*)d_in[8];
    const float* n2g    = (const float*)d_in[9];
    const float* n2b    = (const float*)d_in[10];
    const float* fc1_w  = (const float*)d_in[11];
    const float* fc1_b  = (const float*)d_in[12];
    const float* fc2_w  = (const float*)d_in[13];
    const float* fc2_b  = (const float*)d_in[14];
    float* out = (float*)d_out;

    __half *ph, *pkv, *po, *phid, *pwkv, *pwpr, *pwf1, *pwf2;
    float *py, *pbias;
    cudaGetSymbolAddress((void**)&ph,    g_h);
    cudaGetSymbolAddress((void**)&pkv,   g_kv);
    cudaGetSymbolAddress((void**)&po,    g_o);
    cudaGetSymbolAddress((void**)&py,    g_y);
    cudaGetSymbolAddress((void**)&phid,  g_hid);
    cudaGetSymbolAddress((void**)&pbias, g_bias);
    cudaGetSymbolAddress((void**)&pwkv,  g_wkv);
    cudaGetSymbolAddress((void**)&pwpr,  g_wpr);
    cudaGetSymbolAddress((void**)&pwf1,  g_wf1);
    cudaGetSymbolAddress((void**)&pwf2,  g_wf2);

    // bias + weight prep
    bias_kernel<<<NH_, 256>>>(rpb, pbias);
    dim3 wtb(32, 8);
    wt_kernel<<<dim3(KV_DIM / 32,  C_DIM / 32),   wtb>>>(qkv_w,  pwkv, C_DIM,   KV_DIM);
    wt_kernel<<<dim3(C_DIM / 32,   C_DIM / 32),   wtb>>>(proj_w, pwpr, C_DIM,   C_DIM);
    wt_kernel<<<dim3(HID_DIM / 32, C_DIM / 32),   wtb>>>(fc1_w,  pwf1, C_DIM,   HID_DIM);
    wt_kernel<<<dim3(C_DIM / 32,   HID_DIM / 32), wtb>>>(fc2_w,  pwf2, HID_DIM, C_DIM);

    // LN1 + window partition
    ln_kernel<true><<<M_ROWS / 8, 256>>>(x, n1g, n1b, ph);
    // KV projection
    mm_kernel<0><<<dim3(KV_DIM / 64, M_ROWS / 128), 256>>>(ph, pwkv, qkv_b, pkv, nullptr, KV_DIM, C_DIM);
    // attention
    attn_kernel<<<dim3(2048, NH_), 64>>>(pkv, qg, pbias, po);
    // proj + residual (gathers x)
    mm_kernel<1><<<dim3(C_DIM / 64, M_ROWS / 128), 256>>>(po, pwpr, proj_b, py, x, C_DIM, C_DIM);
    // LN2
    ln_kernel<false><<<M_ROWS / 8, 256>>>(py, n2g, n2b, ph);
    // fc1 + gelu
    mm_kernel<2><<<dim3(HID_DIM / 64, M_ROWS / 128), 256>>>(ph, pwf1, fc1_b, phid, nullptr, HID_DIM, C_DIM);
    // fc2 + residual, scatter to pixel order
    mm_kernel<3><<<dim3(C_DIM / 64, M_ROWS / 128), 256>>>(phid, pwf2, fc2_b, out, py, C_DIM, HID_DIM);
}

// round 9
// speedup vs baseline: 2.6528x; 1.2343x over previous
#include <cuda_runtime.h>
#include <cuda_fp16.h>
#include <mma.h>
#include <math.h>
#include <stdint.h>
#include <stddef.h>

using namespace nvcuda;

// ---------------------------------------------------------------------------
// GCViT block. fp16 WMMA GEMMs + WMMA attention (no inline PTX anywhere).
// Shapes: B=32, H=W=64, C=192, NH=6, hd=32, WS=8, N=64, Bw=2048, M=131072.
// ---------------------------------------------------------------------------

#define M_ROWS   131072
#define C_DIM    192
#define KV_DIM   384
#define HID_DIM  768
#define NH_      6
#define HD_      32

// Scratch (device globals; allocation-free per harness rules)
__device__ __half g_h  [(size_t)M_ROWS * C_DIM];    // LN out (fp16)
__device__ __half g_kv [(size_t)M_ROWS * KV_DIM];   // K|V (fp16)
__device__ __half g_o  [(size_t)M_ROWS * C_DIM];    // attn out (fp16)
__device__ float  g_y  [(size_t)M_ROWS * C_DIM];    // residual-1 (fp32, window order)
__device__ __half g_hid[(size_t)M_ROWS * HID_DIM];  // MLP hidden (fp16)
__device__ float  g_bias[NH_ * 64 * 64];
// transposed fp16 weights [N,K]
__device__ __half g_wkv [KV_DIM  * C_DIM];
__device__ __half g_wpr [C_DIM   * C_DIM];
__device__ __half g_wf1 [HID_DIM * C_DIM];
__device__ __half g_wf2 [C_DIM   * HID_DIM];

__device__ __forceinline__ int remap_row(int r) {
    int w = r >> 6, n = r & 63;
    int b = w >> 6, wy = (w >> 3) & 7, wx = w & 7;
    int iy = n >> 3, ix = n & 7;
    return (b * 64 + wy * 8 + iy) * 64 + wx * 8 + ix;
}

// ---------------------------------------------------------------------------
// bias expand
// ---------------------------------------------------------------------------
__global__ void bias_kernel(const float* __restrict__ rpb, float* __restrict__ bias) {
    int h = blockIdx.x;
    for (int i = threadIdx.x; i < 64 * 64; i += blockDim.x) {
        int n = i >> 6, m = i & 63;
        int ry = (n >> 3) - (m >> 3) + 7;
        int rx = (n & 7) - (m & 7) + 7;
        bias[h * 4096 + i] = rpb[(ry * 15 + rx) * NH_ + h];
    }
}

// ---------------------------------------------------------------------------
// weight transpose + convert: W[K,N] f32 -> Wt[N,K] fp16
// ---------------------------------------------------------------------------
__global__ void wt_kernel(const float* __restrict__ W, __half* __restrict__ Wt,
                          int K, int N) {
    __shared__ float t[32][33];
    int n0 = blockIdx.x * 32, k0 = blockIdx.y * 32;
    int tx = threadIdx.x, ty = threadIdx.y;   // 32 x 8
#pragma unroll
    for (int i = 0; i < 4; i++)
        t[ty * 4 + i][tx] = W[(size_t)(k0 + ty * 4 + i) * N + n0 + tx];
    __syncthreads();
#pragma unroll
    for (int i = 0; i < 4; i++)
        Wt[(size_t)(n0 + ty * 4 + i) * K + k0 + tx] = __float2half(t[tx][ty * 4 + i]);
}

// ---------------------------------------------------------------------------
// LayerNorm -> fp16.  REMAP_IN: gather from pixel order (LN1 + window part.)
// ---------------------------------------------------------------------------
template <bool REMAP_IN>
__global__ void ln_kernel(const float* __restrict__ in,
                          const float* __restrict__ gamma,
                          const float* __restrict__ beta,
                          __half* __restrict__ out) {
    int warp = threadIdx.x >> 5;
    int lane = threadIdx.x & 31;
    int r = blockIdx.x * 8 + warp;
    int in_row = REMAP_IN ? remap_row(r) : r;
    const float* px = in + (size_t)in_row * C_DIM;

    float v[6];
    float s = 0.f, s2 = 0.f;
#pragma unroll
    for (int t = 0; t < 6; t++) {
        v[t] = px[lane + t * 32];
        s += v[t]; s2 += v[t] * v[t];
    }
#pragma unroll
    for (int off = 16; off > 0; off >>= 1) {
        s  += __shfl_xor_sync(0xffffffffu, s,  off);
        s2 += __shfl_xor_sync(0xffffffffu, s2, off);
    }
    float mean = s * (1.f / C_DIM);
    float var  = s2 * (1.f / C_DIM) - mean * mean;
    float rstd = rsqrtf(var + 1e-5f);

    __half* po = out + (size_t)r * C_DIM;
#pragma unroll
    for (int t = 0; t < 6; t++) {
        int c = lane + t * 32;
        po[c] = __float2half((v[t] - mean) * rstd * gamma[c] + beta[c]);
    }
}

// ---------------------------------------------------------------------------
// WMMA GEMM: C[M,N] = A[M,K] @ Bt[N,K]^T.
// BM=128, BK=32, 256 threads, register-prefetch double buffering.
//   BN=128: warps 2(M)x4(N), warp tile 64x32  (kv, fc1)
//   BN= 64: warps 4(M)x2(N), warp tile 32x32  (proj, fc2)
// EPI: 0 kv (+bias -> fp16)         1 proj (+bias + x[remap] -> f32 y)
//      2 fc1 (+bias, gelu -> fp16)  3 fc2 (+bias + y -> f32 out[remap])
// ---------------------------------------------------------------------------
#define A_LD 40     // 32 + 8 halves; row stride 80B (multiple of 16B)

template <int EPI, int BN>
__global__ __launch_bounds__(256)
void mm_kernel(const __half* __restrict__ A, const __half* __restrict__ Bt,
               const float* __restrict__ bias, void* __restrict__ Cout,
               const float* __restrict__ res, int N, int K) {
    constexpr int WARPS_M = (BN == 128) ? 2 : 4;
    constexpr int WTM = 128 / WARPS_M;          // 64 or 32
    constexpr int MF  = WTM / 16;               // 4 or 2
    constexpr int S_LD = BN + 4;
    constexpr int PB  = BN / 64;                // B prefetch regs (2 or 1)

    __shared__ __align__(16) char smraw[20480 + BN * 160];
    __half* As = (__half*)smraw;                       // [2][128*A_LD]
    __half* Bs = (__half*)(smraw + 20480);             // [2][BN*A_LD]
    float*  stg = (float*)smraw;                       // epilogue: 64 x S_LD

    const int tid = threadIdx.x;
    const int wid = tid >> 5;
    const int bm = blockIdx.y * 128;
    const int bn = blockIdx.x * BN;
    const int wm = (wid % WARPS_M) * WTM;
    const int wn = (wid / WARPS_M) * 32;

    wmma::fragment<wmma::accumulator, 16, 16, 16, float> acc[MF][2];
#pragma unroll
    for (int mt = 0; mt < MF; mt++)
#pragma unroll
        for (int nt = 0; nt < 2; nt++) wmma::fill_fragment(acc[mt][nt], 0.f);

    const int nc = K >> 5;   // K/32

    const int arow0 = tid >> 2, aseg0 = tid & 3;

    // ---- chunk 0 direct to buffer 0
    {
#pragma unroll
        for (int i = 0; i < 2; i++) {
            int row = arow0 + i * 64;
            *(float4*)(As + row * A_LD + aseg0 * 8) =
                *(const float4*)(A + (size_t)(bm + row) * K + aseg0 * 8);
        }
#pragma unroll
        for (int i = 0; i < PB; i++) {
            int idx = tid + i * 256;
            int row = idx >> 2, seg = idx & 3;
            *(float4*)(Bs + row * A_LD + seg * 8) =
                *(const float4*)(Bt + (size_t)(bn + row) * K + seg * 8);
        }
    }
    __syncthreads();

    float4 pa[2], pb[PB];
    for (int c = 0; c < nc; c++) {
        int cur = c & 1;
        if (c + 1 < nc) {
            int koff = (c + 1) * 32;
#pragma unroll
            for (int i = 0; i < 2; i++) {
                int row = arow0 + i * 64;
                pa[i] = *(const float4*)(A + (size_t)(bm + row) * K + koff + aseg0 * 8);
            }
#pragma unroll
            for (int i = 0; i < PB; i++) {
                int idx = tid + i * 256;
                int row = idx >> 2, seg = idx & 3;
                pb[i] = *(const float4*)(Bt + (size_t)(bn + row) * K + koff + seg * 8);
            }
        }

        const __half* Ac = As + cur * 128 * A_LD;
        const __half* Bc = Bs + cur * BN * A_LD;
#pragma unroll
        for (int ks = 0; ks < 2; ks++) {
            wmma::fragment<wmma::matrix_a, 16, 16, 16, __half, wmma::row_major> af[MF];
            wmma::fragment<wmma::matrix_b, 16, 16, 16, __half, wmma::col_major> bf[2];
#pragma unroll
            for (int mt = 0; mt < MF; mt++)
                wmma::load_matrix_sync(af[mt], Ac + (wm + mt * 16) * A_LD + ks * 16, A_LD);
#pragma unroll
            for (int nt = 0; nt < 2; nt++)
                wmma::load_matrix_sync(bf[nt], Bc + (wn + nt * 16) * A_LD + ks * 16, A_LD);
#pragma unroll
            for (int mt = 0; mt < MF; mt++)
#pragma unroll
                for (int nt = 0; nt < 2; nt++)
                    wmma::mma_sync(acc[mt][nt], af[mt], bf[nt], acc[mt][nt]);
        }

        if (c + 1 < nc) {
            int nxt = cur ^ 1;
            __half* An = As + nxt * 128 * A_LD;
            __half* Bn = Bs + nxt * BN * A_LD;
#pragma unroll
            for (int i = 0; i < 2; i++) {
                int row = arow0 + i * 64;
                *(float4*)(An + row * A_LD + aseg0 * 8) = pa[i];
            }
#pragma unroll
            for (int i = 0; i < PB; i++) {
                int idx = tid + i * 256;
                int row = idx >> 2, seg = idx & 3;
                *(float4*)(Bn + row * A_LD + seg * 8) = pb[i];
            }
        }
        __syncthreads();
    }

    // ---- epilogue: two M-passes (64 rows each) via f32 smem staging
#pragma unroll
    for (int p = 0; p < 2; p++) {
        if ((wm >> 6) == p) {
            int wrow = wm & 63;
#pragma unroll
            for (int mt = 0; mt < MF; mt++)
#pragma unroll
                for (int nt = 0; nt < 2; nt++)
                    wmma::store_matrix_sync(stg + (wrow + mt * 16) * S_LD + wn + nt * 16,
                                            acc[mt][nt], S_LD, wmma::mem_row_major);
        }
        __syncthreads();

        constexpr int RPT = BN / 4;           // rows per thread-group pass
        int col = tid % BN;
        int rg  = tid / BN;
        int gc  = bn + col;
        float bv = bias[gc];
#pragma unroll
        for (int j = 0; j < RPT; j++) {
            int row  = rg * RPT + j;
            int grow = bm + p * 64 + row;
            float v  = stg[row * S_LD + col] + bv;
            if (EPI == 0) {
                ((__half*)Cout)[(size_t)grow * N + gc] = __float2half(v);
            } else if (EPI == 1) {
                int prow = remap_row(grow);
                ((float*)Cout)[(size_t)grow * N + gc] = v + res[(size_t)prow * N + gc];
            } else if (EPI == 2) {
                float g = 0.5f * v * (1.f + erff(v * 0.70710678118654752f));
                ((__half*)Cout)[(size_t)grow * N + gc] = __float2half(g);
            } else {
                int prow = remap_row(grow);
                ((float*)Cout)[(size_t)prow * N + gc] = v + res[(size_t)grow * N + gc];
            }
        }
        __syncthreads();
    }
}

// ---------------------------------------------------------------------------
// WMMA attention: block = one (window, head), 128 threads (4 warps).
// S = Q K^T on tensor cores; fp32 softmax (no max-subtraction, logits O(0.3));
// O = P V on tensor cores with unnormalized P; 1/sum applied at the store.
// ---------------------------------------------------------------------------
__global__ __launch_bounds__(128)
void attn_kernel(const __half* __restrict__ kv, const float* __restrict__ qg,
                 const float* __restrict__ bias, __half* __restrict__ obuf) {
    __shared__ __align__(16) __half Qs[64 * A_LD];
    __shared__ __align__(16) __half Ks[64 * A_LD];
    __shared__ __align__(16) __half Vs[64 * A_LD];
    __shared__ __align__(16) float  Ss[64 * 68];
    __shared__ __align__(16) __half Ps[64 * 72];
    __shared__ float sinv[64];

    const int tid = threadIdx.x;
    const int wid = tid >> 5;
    const int w = blockIdx.x;
    const int h = blockIdx.y;
    const int b = w >> 6;
    const float scale = 0.17677669529663687f;   // 1/sqrt(32)

    // ---- load Q (f32 -> fp16 * scale), K, V into smem
    {
        int n = tid >> 1;
        int c0 = (tid & 1) * 16;
        const float* qrow = qg + ((size_t)(b * 64 + n) * NH_ + h) * HD_ + c0;
        __half* qd = Qs + n * A_LD + c0;
#pragma unroll
        for (int j = 0; j < 16; j++) qd[j] = __float2half(qrow[j] * scale);
        const __half* kvrow = kv + (size_t)(w * 64 + n) * KV_DIM + h * HD_ + c0;
        *(float4*)(Ks + n * A_LD + c0)     = *(const float4*)(kvrow);
        *(float4*)(Ks + n * A_LD + c0 + 8) = *(const float4*)(kvrow + 8);
        *(float4*)(Vs + n * A_LD + c0)     = *(const float4*)(kvrow + C_DIM);
        *(float4*)(Vs + n * A_LD + c0 + 8) = *(const float4*)(kvrow + C_DIM + 8);
    }
    __syncthreads();

    // ---- S = Q K^T  (each warp: 16 query rows x 64 keys)
    {
        const int r0 = wid * 16;
        wmma::fragment<wmma::accumulator, 16, 16, 16, float> sacc[4];
#pragma unroll
        for (int mt = 0; mt < 4; mt++) wmma::fill_fragment(sacc[mt], 0.f);
#pragma unroll
        for (int kf = 0; kf < 2; kf++) {
            wmma::fragment<wmma::matrix_a, 16, 16, 16, __half, wmma::row_major> af;
            wmma::load_matrix_sync(af, Qs + r0 * A_LD + kf * 16, A_LD);
#pragma unroll
            for (int mt = 0; mt < 4; mt++) {
                wmma::fragment<wmma::matrix_b, 16, 16, 16, __half, wmma::col_major> bf;
                wmma::load_matrix_sync(bf, Ks + (mt * 16) * A_LD + kf * 16, A_LD);
                wmma::mma_sync(sacc[mt], af, bf, sacc[mt]);
            }
        }
#pragma unroll
        for (int mt = 0; mt < 4; mt++)
            wmma::store_matrix_sync(Ss + r0 * 68 + mt * 16, sacc[mt], 68, wmma::mem_row_major);
    }
    __syncthreads();

    // ---- softmax (fp32, unnormalized): P = exp(S + bias), sinv = 1/rowsum
    {
        int row = tid >> 1;
        int c0 = (tid & 1) * 32;
        const float* brow = bias + (h * 64 + row) * 64 + c0;
        const float* srow = Ss + row * 68 + c0;
        __half* prow = Ps + row * 72 + c0;
        float s = 0.f;
#pragma unroll
        for (int j = 0; j < 32; j++) {
            float e = __expf(srow[j] + brow[j]);
            s += e;
            prow[j] = __float2half(e);
        }
        float tot = s + __shfl_xor_sync(0xffffffffu, s, 1);
        if ((tid & 1) == 0) sinv[row] = 1.f / tot;
    }
    __syncthreads();

    // ---- O = P V  (each warp: 16 rows x 32 dims)
    {
        const int r0 = wid * 16;
        wmma::fragment<wmma::accumulator, 16, 16, 16, float> oacc[2];
#pragma unroll
        for (int nt = 0; nt < 2; nt++) wmma::fill_fragment(oacc[nt], 0.f);
#pragma unroll
        for (int kf = 0; kf < 4; kf++) {
            wmma::fragment<wmma::matrix_a, 16, 16, 16, __half, wmma::row_major> af;
            wmma::load_matrix_sync(af, Ps + r0 * 72 + kf * 16, 72);
#pragma unroll
            for (int nt = 0; nt < 2; nt++) {
                wmma::fragment<wmma::matrix_b, 16, 16, 16, __half, wmma::row_major> bf;
                wmma::load_matrix_sync(bf, Vs + (kf * 16) * A_LD + nt * 16, A_LD);
                wmma::mma_sync(oacc[nt], af, bf, oacc[nt]);
            }
        }
#pragma unroll
        for (int nt = 0; nt < 2; nt++)
            wmma::store_matrix_sync(Ss + r0 * 68 + nt * 16, oacc[nt], 68, wmma::mem_row_major);
    }
    __syncthreads();

    // ---- write O * 1/rowsum
    {
        int row = tid >> 1;
        int c0 = (tid & 1) * 16;
        float inv = sinv[row];
        __half* orow = obuf + (size_t)(w * 64 + row) * C_DIM + h * HD_ + c0;
        const float* srow = Ss + row * 68 + c0;
#pragma unroll
        for (int j = 0; j < 16; j++) orow[j] = __float2half(srow[j] * inv);
    }
}

// ---------------------------------------------------------------------------
// launch
// ---------------------------------------------------------------------------
extern "C" void kernel_launch(void* const* d_in, const int* in_sizes, int n_in,
                              void* d_out, int out_size) {
    const float* x      = (const float*)d_in[0];
    const float* qg     = (const float*)d_in[1];
    const float* n1g    = (const float*)d_in[2];
    const float* n1b    = (const float*)d_in[3];
    const float* qkv_w  = (const float*)d_in[4];
    const float* qkv_b  = (const float*)d_in[5];
    const float* rpb    = (const float*)d_in[6];
    const float* proj_w = (const float*)d_in[7];
    const float* proj_b = (const float*)d_in[8];
    const float* n2g    = (const float*)d_in[9];
    const float* n2b    = (const float*)d_in[10];
    const float* fc1_w  = (const float*)d_in[11];
    const float* fc1_b  = (const float*)d_in[12];
    const float* fc2_w  = (const float*)d_in[13];
    const float* fc2_b  = (const float*)d_in[14];
    float* out = (float*)d_out;

    __half *ph, *pkv, *po, *phid, *pwkv, *pwpr, *pwf1, *pwf2;
    float *py, *pbias;
    cudaGetSymbolAddress((void**)&ph,    g_h);
    cudaGetSymbolAddress((void**)&pkv,   g_kv);
    cudaGetSymbolAddress((void**)&po,    g_o);
    cudaGetSymbolAddress((void**)&py,    g_y);
    cudaGetSymbolAddress((void**)&phid,  g_hid);
    cudaGetSymbolAddress((void**)&pbias, g_bias);
    cudaGetSymbolAddress((void**)&pwkv,  g_wkv);
    cudaGetSymbolAddress((void**)&pwpr,  g_wpr);
    cudaGetSymbolAddress((void**)&pwf1,  g_wf1);
    cudaGetSymbolAddress((void**)&pwf2,  g_wf2);

    // bias + weight prep
    bias_kernel<<<NH_, 256>>>(rpb, pbias);
    dim3 wtb(32, 8);
    wt_kernel<<<dim3(KV_DIM / 32,  C_DIM / 32),   wtb>>>(qkv_w,  pwkv, C_DIM,   KV_DIM);
    wt_kernel<<<dim3(C_DIM / 32,   C_DIM / 32),   wtb>>>(proj_w, pwpr, C_DIM,   C_DIM);
    wt_kernel<<<dim3(HID_DIM / 32, C_DIM / 32),   wtb>>>(fc1_w,  pwf1, C_DIM,   HID_DIM);
    wt_kernel<<<dim3(C_DIM / 32,   HID_DIM / 32), wtb>>>(fc2_w,  pwf2, HID_DIM, C_DIM);

    // LN1 + window partition
    ln_kernel<true><<<M_ROWS / 8, 256>>>(x, n1g, n1b, ph);
    // KV projection (N=384 -> BN=128)
    mm_kernel<0, 128><<<dim3(KV_DIM / 128, M_ROWS / 128), 256>>>(ph, pwkv, qkv_b, pkv, nullptr, KV_DIM, C_DIM);
    // attention (tensor-core)
    attn_kernel<<<dim3(2048, NH_), 128>>>(pkv, qg, pbias, po);
    // proj + residual (N=192 -> BN=64)
    mm_kernel<1, 64><<<dim3(C_DIM / 64, M_ROWS / 128), 256>>>(po, pwpr, proj_b, py, x, C_DIM, C_DIM);
    // LN2
    ln_kernel<false><<<M_ROWS / 8, 256>>>(py, n2g, n2b, ph);
    // fc1 + gelu (N=768 -> BN=128)
    mm_kernel<2, 128><<<dim3(HID_DIM / 128, M_ROWS / 128), 256>>>(ph, pwf1, fc1_b, phid, nullptr, HID_DIM, C_DIM);
    // fc2 + residual, scatter to pixel order (N=192 -> BN=64)
    mm_kernel<3, 64><<<dim3(C_DIM / 64, M_ROWS / 128), 256>>>(phid, pwf2, fc2_b, out, py, C_DIM, HID_DIM);
}